// round 8
// baseline (speedup 1.0000x reference)
#include <cuda_runtime.h>
#include <cstdint>
#include <math.h>

// Problem constants
#define BB 4
#define SS 2048
#define DD 1024
#define HH 8
#define DHH 128
#define DFF 4096
#define ROWS (BB*SS)   // 8192

// -------- scratch buffers (device globals; no allocation allowed) --------
// IMPORTANT: these are ONLY ever referenced from device code (template-selected
// inside kernels). Never passed by name from host code — the host shadow
// symbol is a host address (GB300 ATS makes it silently dereferenceable!).
__device__ float g_qkv [ROWS * 3 * DD];   // 96 MB
__device__ float g_attn[ROWS * DD];       // 32 MB
__device__ float g_x   [ROWS * DD];       // 32 MB
__device__ float g_ff1 [ROWS * DFF];      // 128 MB
__device__ float g_tmp [ROWS * DD];       // 32 MB

// ============================================================================
// SGEMM: C[M,N] = A[M,K] @ B[K,N]  (+bias, +relu per EPI flag)
// A selected by ASEL: 0=arg, 1=g_attn, 2=g_x, 3=g_ff1
// C selected by CSEL: 0=g_qkv, 1=g_tmp, 2=g_ff1
// 128x128 block tile, BK=8, 256 threads, 8x8 micro-tile split as 2x(4-wide)
// halves at column offsets {tx*4, 64+tx*4} for conflict-free broadcast LDS.
// ============================================================================
template<int EPI, int ASEL, int CSEL>
__global__ __launch_bounds__(256) void sgemm_kernel(
    const float* __restrict__ Aarg, const float* __restrict__ B,
    const float* __restrict__ bias, int M, int N, int K)
{
    const float* __restrict__ A =
        (ASEL == 0) ? Aarg : (ASEL == 1) ? g_attn : (ASEL == 2) ? g_x : g_ff1;
    float* __restrict__ C =
        (CSEL == 0) ? g_qkv : (CSEL == 1) ? g_tmp : g_ff1;

    __shared__ float As[8][128];
    __shared__ float Bs[8][128];

    const int tid = threadIdx.x;
    const int bx = blockIdx.x, by = blockIdx.y;
    const int tx = tid & 15;      // N direction (16)
    const int ty = tid >> 4;      // M direction (16)

    const int arow = tid >> 1;           // 0..127
    const int acol = (tid & 1) * 4;      // 0 or 4
    const int brow = tid >> 5;           // 0..7
    const int bcol = (tid & 31) * 4;     // 0..124

    const float* Ab = A + (size_t)by * 128 * K;
    const float* Bb = B + (size_t)bx * 128;

    float acc[8][8];
#pragma unroll
    for (int i = 0; i < 8; i++)
#pragma unroll
        for (int j = 0; j < 8; j++) acc[i][j] = 0.f;

    for (int k0 = 0; k0 < K; k0 += 8) {
        float4 av = *(const float4*)(Ab + (size_t)arow * K + k0 + acol);
        As[acol + 0][arow] = av.x;
        As[acol + 1][arow] = av.y;
        As[acol + 2][arow] = av.z;
        As[acol + 3][arow] = av.w;
        *(float4*)&Bs[brow][bcol] =
            *(const float4*)(Bb + (size_t)(k0 + brow) * N + bcol);
        __syncthreads();

#pragma unroll
        for (int k = 0; k < 8; k++) {
            float4 a0 = ((const float4*)As[k])[ty];
            float4 a1 = ((const float4*)As[k])[16 + ty];
            float4 b0 = ((const float4*)Bs[k])[tx];
            float4 b1 = ((const float4*)Bs[k])[16 + tx];
            float ar[8] = {a0.x,a0.y,a0.z,a0.w, a1.x,a1.y,a1.z,a1.w};
            float br[8] = {b0.x,b0.y,b0.z,b0.w, b1.x,b1.y,b1.z,b1.w};
#pragma unroll
            for (int i = 0; i < 8; i++)
#pragma unroll
                for (int j = 0; j < 8; j++)
                    acc[i][j] = fmaf(ar[i], br[j], acc[i][j]);
        }
        __syncthreads();
    }

    // epilogue: rows {ty*4+i, 64+ty*4+i}, cols {tx*4+j, 64+tx*4+j}
#pragma unroll
    for (int ih = 0; ih < 2; ih++) {
#pragma unroll
        for (int i = 0; i < 4; i++) {
            int rrow = by * 128 + ih * 64 + ty * 4 + i;
            float* crow = C + (size_t)rrow * N + bx * 128;
#pragma unroll
            for (int jh = 0; jh < 2; jh++) {
                int c0 = jh * 64 + tx * 4;
                float4 v;
                v.x = acc[ih*4 + i][jh*4 + 0];
                v.y = acc[ih*4 + i][jh*4 + 1];
                v.z = acc[ih*4 + i][jh*4 + 2];
                v.w = acc[ih*4 + i][jh*4 + 3];
                if (EPI >= 1) {
                    float4 bv = *(const float4*)(bias + bx * 128 + c0);
                    v.x += bv.x; v.y += bv.y; v.z += bv.z; v.w += bv.w;
                    if (EPI == 2) {
                        v.x = fmaxf(v.x, 0.f); v.y = fmaxf(v.y, 0.f);
                        v.z = fmaxf(v.z, 0.f); v.w = fmaxf(v.w, 0.f);
                    }
                }
                *(float4*)(crow + c0) = v;
            }
        }
    }
}

// ============================================================================
// Causal flash attention. Grid (S/64, H, B), 256 threads.
// Thread (row=tid/4, quad=tid&3) owns cols {quad*4 + 16*cc} (8 float4 chunks).
// Q,O in registers; K,V 32-key tiles in smem; online softmax.
// Reads g_qkv, writes g_attn (device symbols, referenced in device code).
// ============================================================================
__global__ __launch_bounds__(256) void attn_kernel()
{
    __shared__ float4 Kt[32][32];   // [key][128 floats as 32 float4]
    __shared__ float4 Vt[32][32];

    const float* __restrict__ qkv = g_qkv;
    float* __restrict__ out = g_attn;

    const int b = blockIdx.z, h = blockIdx.y, qt = blockIdx.x;
    const int tid = threadIdx.x;
    const int row = tid >> 2, quad = tid & 3;
    const int qrow = qt * 64 + row;
    const float scale = 0.08838834764831845f;   // 1/sqrt(128)

    const float* qbase = qkv + (size_t)(b * SS + qrow) * (3 * DD) + h * DHH;
    float4 q[8];
#pragma unroll
    for (int cc = 0; cc < 8; cc++) {
        float4 t = *(const float4*)(qbase + cc * 16 + quad * 4);
        t.x *= scale; t.y *= scale; t.z *= scale; t.w *= scale;
        q[cc] = t;
    }

    float4 o[8];
#pragma unroll
    for (int cc = 0; cc < 8; cc++) o[cc] = make_float4(0.f, 0.f, 0.f, 0.f);
    float m = -1e30f, l = 0.f;

    const int ntiles = 2 * qt + 2;   // keys [0, 64*qt+64) cover all qrow in tile
    for (int kt = 0; kt < ntiles; kt++) {
        const int kb = kt * 32;
        __syncthreads();
#pragma unroll
        for (int i = 0; i < 4; i++) {
            int f = tid + i * 256;
            int r = f >> 5, c = f & 31;
            size_t grow = (size_t)(b * SS + kb + r) * (3 * DD) + h * DHH;
            Kt[r][c] = *(const float4*)(qkv + grow + DD + c * 4);
            Vt[r][c] = *(const float4*)(qkv + grow + 2 * DD + c * 4);
        }
        __syncthreads();

        float s[32];
#pragma unroll
        for (int j = 0; j < 32; j++) {
            float a = 0.f;
#pragma unroll
            for (int cc = 0; cc < 8; cc++) {
                float4 kv = Kt[j][cc * 4 + quad];
                a = fmaf(q[cc].x, kv.x, a);
                a = fmaf(q[cc].y, kv.y, a);
                a = fmaf(q[cc].z, kv.z, a);
                a = fmaf(q[cc].w, kv.w, a);
            }
            a += __shfl_xor_sync(0xffffffffu, a, 1);
            a += __shfl_xor_sync(0xffffffffu, a, 2);
            s[j] = a;
        }
        if (kb + 31 > qrow) {
#pragma unroll
            for (int j = 0; j < 32; j++)
                if (kb + j > qrow) s[j] = -1e30f;
        }
        float mnew = m;
#pragma unroll
        for (int j = 0; j < 32; j++) mnew = fmaxf(mnew, s[j]);
        float corr = __expf(m - mnew);
        m = mnew;
        l *= corr;
#pragma unroll
        for (int cc = 0; cc < 8; cc++) {
            o[cc].x *= corr; o[cc].y *= corr; o[cc].z *= corr; o[cc].w *= corr;
        }
#pragma unroll
        for (int j = 0; j < 32; j++) {
            float p = __expf(s[j] - mnew);
            l += p;
            s[j] = p;
        }
#pragma unroll
        for (int j = 0; j < 32; j++) {
            float p = s[j];
#pragma unroll
            for (int cc = 0; cc < 8; cc++) {
                float4 vv = Vt[j][cc * 4 + quad];
                o[cc].x = fmaf(p, vv.x, o[cc].x);
                o[cc].y = fmaf(p, vv.y, o[cc].y);
                o[cc].z = fmaf(p, vv.z, o[cc].z);
                o[cc].w = fmaf(p, vv.w, o[cc].w);
            }
        }
    }

    float inv = 1.f / l;
    float* ob = out + (size_t)(b * SS + qrow) * DD + h * DHH;
#pragma unroll
    for (int cc = 0; cc < 8; cc++) {
        float4 v = o[cc];
        v.x *= inv; v.y *= inv; v.z *= inv; v.w *= inv;
        *(float4*)(ob + cc * 16 + quad * 4) = v;
    }
}

// ============================================================================
// Residual-add + LayerNorm, row length 1024, one block/row, 256 threads.
// MODE 0: g_x = LN(aArg + g_tmp)          (aArg = src)
// MODE 1: outArg = LN(g_x + g_tmp)
// Scratch buffers resolved in device code; only harness pointers are args.
// ============================================================================
template<int MODE>
__global__ __launch_bounds__(256) void add_ln_kernel(
    const float* __restrict__ aArg, const float* __restrict__ g,
    const float* __restrict__ beta, float* __restrict__ outArg)
{
    const float* __restrict__ a = (MODE == 0) ? aArg : g_x;
    const float* __restrict__ r = g_tmp;
    float* __restrict__ out = (MODE == 0) ? g_x : outArg;

    __shared__ float red[16];
    const int row = blockIdx.x;
    const int tid = threadIdx.x;

    const float4 va = ((const float4*)(a + (size_t)row * DD))[tid];
    const float4 vr = ((const float4*)(r + (size_t)row * DD))[tid];
    float v0 = va.x + vr.x, v1 = va.y + vr.y, v2 = va.z + vr.z, v3 = va.w + vr.w;

    float s  = v0 + v1 + v2 + v3;
    float sq = v0*v0 + v1*v1 + v2*v2 + v3*v3;
#pragma unroll
    for (int off = 16; off; off >>= 1) {
        s  += __shfl_xor_sync(0xffffffffu, s,  off);
        sq += __shfl_xor_sync(0xffffffffu, sq, off);
    }
    if ((tid & 31) == 0) { red[tid >> 5] = s; red[8 + (tid >> 5)] = sq; }
    __syncthreads();
    s  = red[0] + red[1] + red[2] + red[3] + red[4] + red[5] + red[6] + red[7];
    sq = red[8] + red[9] + red[10] + red[11] + red[12] + red[13] + red[14] + red[15];

    const float mean = s * (1.f / 1024.f);
    const float var  = sq * (1.f / 1024.f) - mean * mean;
    const float inv  = rsqrtf(var + 1e-5f);

    const int col = tid * 4;
    const float4 gg = *(const float4*)(g + col);
    const float4 bb = *(const float4*)(beta + col);
    float4 ov;
    ov.x = (v0 - mean) * inv * gg.x + bb.x;
    ov.y = (v1 - mean) * inv * gg.y + bb.y;
    ov.z = (v2 - mean) * inv * gg.z + bb.z;
    ov.w = (v3 - mean) * inv * gg.w + bb.w;
    ((float4*)(out + (size_t)row * DD))[tid] = ov;
}

// ============================================================================
// launch — kernel launches only; scratch never crosses the host boundary
// ============================================================================
extern "C" void kernel_launch(void* const* d_in, const int* in_sizes, int n_in,
                              void* d_out, int out_size)
{
    const float* src   = (const float*)d_in[0];
    const float* w_qkv = (const float*)d_in[1];
    const float* w_out = (const float*)d_in[2];
    const float* w1    = (const float*)d_in[3];
    const float* b1    = (const float*)d_in[4];
    const float* w2    = (const float*)d_in[5];
    const float* b2    = (const float*)d_in[6];
    const float* g1    = (const float*)d_in[7];
    const float* beta1 = (const float*)d_in[8];
    const float* g2    = (const float*)d_in[9];
    const float* beta2 = (const float*)d_in[10];
    float* out = (float*)d_out;

    // 1) g_qkv = src @ w_qkv                       [8192,3072]
    sgemm_kernel<0,0,0><<<dim3(3*DD/128, ROWS/128), 256>>>(src, w_qkv, nullptr,
                                                           ROWS, 3*DD, DD);
    // 2) g_attn = causal_flash_attention(g_qkv)    [8192,1024]
    attn_kernel<<<dim3(SS/64, HH, BB), 256>>>();
    // 3) g_tmp = g_attn @ w_out
    sgemm_kernel<0,1,1><<<dim3(DD/128, ROWS/128), 256>>>(nullptr, w_out, nullptr,
                                                         ROWS, DD, DD);
    // 4) g_x = LN(src + g_tmp)
    add_ln_kernel<0><<<ROWS, 256>>>(src, g1, beta1, nullptr);
    // 5) g_ff1 = relu(g_x @ w1 + b1)
    sgemm_kernel<2,2,2><<<dim3(DFF/128, ROWS/128), 256>>>(nullptr, w1, b1,
                                                          ROWS, DFF, DD);
    // 6) g_tmp = g_ff1 @ w2 + b2
    sgemm_kernel<1,3,1><<<dim3(DD/128, ROWS/128), 256>>>(nullptr, w2, b2,
                                                         ROWS, DD, DFF);
    // 7) out = LN(g_x + g_tmp)
    add_ln_kernel<1><<<ROWS, 256>>>(nullptr, g2, beta2, out);
}

// round 14
// speedup vs baseline: 1.0010x; 1.0010x over previous
#include <cuda_runtime.h>
#include <cstdint>
#include <math.h>

// Problem constants
#define BB 4
#define SS 2048
#define DD 1024
#define HH 8
#define DHH 128
#define DFF 4096
#define ROWS (BB*SS)   // 8192

// -------- scratch buffers (device globals; no allocation allowed) --------
// IMPORTANT: these are ONLY ever referenced from device code (template-selected
// inside kernels). Never passed by name from host code — the host shadow
// symbol is a host address (GB300 ATS makes it silently dereferenceable!).
__device__ float g_qkv [ROWS * 3 * DD];   // 96 MB
__device__ float g_attn[ROWS * DD];       // 32 MB
__device__ float g_x   [ROWS * DD];       // 32 MB
__device__ float g_ff1 [ROWS * DFF];      // 128 MB
__device__ float g_tmp [ROWS * DD];       // 32 MB

// ============================================================================
// SGEMM: C[M,N] = A[M,K] @ B[K,N]  (+bias, +relu per EPI flag)
// A selected by ASEL: 0=arg, 1=g_attn, 2=g_x, 3=g_ff1
// C selected by CSEL: 0=g_qkv, 1=g_tmp, 2=g_ff1
// 128x128 block tile, BK=8, 256 threads, 8x8 micro-tile split as 2x(4-wide)
// halves at column offsets {tx*4, 64+tx*4} for conflict-free broadcast LDS.
// ============================================================================
template<int EPI, int ASEL, int CSEL>
__global__ __launch_bounds__(256) void sgemm_kernel(
    const float* __restrict__ Aarg, const float* __restrict__ B,
    const float* __restrict__ bias, int M, int N, int K)
{
    const float* __restrict__ A =
        (ASEL == 0) ? Aarg : (ASEL == 1) ? g_attn : (ASEL == 2) ? g_x : g_ff1;
    float* __restrict__ C =
        (CSEL == 0) ? g_qkv : (CSEL == 1) ? g_tmp : g_ff1;

    __shared__ float As[8][128];
    __shared__ float Bs[8][128];

    const int tid = threadIdx.x;
    const int bx = blockIdx.x, by = blockIdx.y;
    const int tx = tid & 15;      // N direction (16)
    const int ty = tid >> 4;      // M direction (16)

    const int arow = tid >> 1;           // 0..127
    const int acol = (tid & 1) * 4;      // 0 or 4
    const int brow = tid >> 5;           // 0..7
    const int bcol = (tid & 31) * 4;     // 0..124

    const float* Ab = A + (size_t)by * 128 * K;
    const float* Bb = B + (size_t)bx * 128;

    float acc[8][8];
#pragma unroll
    for (int i = 0; i < 8; i++)
#pragma unroll
        for (int j = 0; j < 8; j++) acc[i][j] = 0.f;

    for (int k0 = 0; k0 < K; k0 += 8) {
        float4 av = *(const float4*)(Ab + (size_t)arow * K + k0 + acol);
        As[acol + 0][arow] = av.x;
        As[acol + 1][arow] = av.y;
        As[acol + 2][arow] = av.z;
        As[acol + 3][arow] = av.w;
        *(float4*)&Bs[brow][bcol] =
            *(const float4*)(Bb + (size_t)(k0 + brow) * N + bcol);
        __syncthreads();

#pragma unroll
        for (int k = 0; k < 8; k++) {
            float4 a0 = ((const float4*)As[k])[ty];
            float4 a1 = ((const float4*)As[k])[16 + ty];
            float4 b0 = ((const float4*)Bs[k])[tx];
            float4 b1 = ((const float4*)Bs[k])[16 + tx];
            float ar[8] = {a0.x,a0.y,a0.z,a0.w, a1.x,a1.y,a1.z,a1.w};
            float br[8] = {b0.x,b0.y,b0.z,b0.w, b1.x,b1.y,b1.z,b1.w};
#pragma unroll
            for (int i = 0; i < 8; i++)
#pragma unroll
                for (int j = 0; j < 8; j++)
                    acc[i][j] = fmaf(ar[i], br[j], acc[i][j]);
        }
        __syncthreads();
    }

    // epilogue: rows {ty*4+i, 64+ty*4+i}, cols {tx*4+j, 64+tx*4+j}
#pragma unroll
    for (int ih = 0; ih < 2; ih++) {
#pragma unroll
        for (int i = 0; i < 4; i++) {
            int rrow = by * 128 + ih * 64 + ty * 4 + i;
            float* crow = C + (size_t)rrow * N + bx * 128;
#pragma unroll
            for (int jh = 0; jh < 2; jh++) {
                int c0 = jh * 64 + tx * 4;
                float4 v;
                v.x = acc[ih*4 + i][jh*4 + 0];
                v.y = acc[ih*4 + i][jh*4 + 1];
                v.z = acc[ih*4 + i][jh*4 + 2];
                v.w = acc[ih*4 + i][jh*4 + 3];
                if (EPI >= 1) {
                    float4 bv = *(const float4*)(bias + bx * 128 + c0);
                    v.x += bv.x; v.y += bv.y; v.z += bv.z; v.w += bv.w;
                    if (EPI == 2) {
                        v.x = fmaxf(v.x, 0.f); v.y = fmaxf(v.y, 0.f);
                        v.z = fmaxf(v.z, 0.f); v.w = fmaxf(v.w, 0.f);
                    }
                }
                *(float4*)(crow + c0) = v;
            }
        }
    }
}

// ============================================================================
// Causal flash attention. Grid (S/64, H, B), 256 threads.
// Thread (row=tid/4, quad=tid&3) owns cols {quad*4 + 16*cc} (8 float4 chunks).
// Q,O in registers; K,V 32-key tiles in smem; online softmax.
// Reads g_qkv, writes g_attn (device symbols, referenced in device code).
// ============================================================================
__global__ __launch_bounds__(256) void attn_kernel()
{
    __shared__ float4 Kt[32][32];   // [key][128 floats as 32 float4]
    __shared__ float4 Vt[32][32];

    const float* __restrict__ qkv = g_qkv;
    float* __restrict__ out = g_attn;

    const int b = blockIdx.z, h = blockIdx.y, qt = blockIdx.x;
    const int tid = threadIdx.x;
    const int row = tid >> 2, quad = tid & 3;
    const int qrow = qt * 64 + row;
    const float scale = 0.08838834764831845f;   // 1/sqrt(128)

    const float* qbase = qkv + (size_t)(b * SS + qrow) * (3 * DD) + h * DHH;
    float4 q[8];
#pragma unroll
    for (int cc = 0; cc < 8; cc++) {
        float4 t = *(const float4*)(qbase + cc * 16 + quad * 4);
        t.x *= scale; t.y *= scale; t.z *= scale; t.w *= scale;
        q[cc] = t;
    }

    float4 o[8];
#pragma unroll
    for (int cc = 0; cc < 8; cc++) o[cc] = make_float4(0.f, 0.f, 0.f, 0.f);
    float m = -1e30f, l = 0.f;

    const int ntiles = 2 * qt + 2;   // keys [0, 64*qt+64) cover all qrow in tile
    for (int kt = 0; kt < ntiles; kt++) {
        const int kb = kt * 32;
        __syncthreads();
#pragma unroll
        for (int i = 0; i < 4; i++) {
            int f = tid + i * 256;
            int r = f >> 5, c = f & 31;
            size_t grow = (size_t)(b * SS + kb + r) * (3 * DD) + h * DHH;
            Kt[r][c] = *(const float4*)(qkv + grow + DD + c * 4);
            Vt[r][c] = *(const float4*)(qkv + grow + 2 * DD + c * 4);
        }
        __syncthreads();

        float s[32];
#pragma unroll
        for (int j = 0; j < 32; j++) {
            float a = 0.f;
#pragma unroll
            for (int cc = 0; cc < 8; cc++) {
                float4 kv = Kt[j][cc * 4 + quad];
                a = fmaf(q[cc].x, kv.x, a);
                a = fmaf(q[cc].y, kv.y, a);
                a = fmaf(q[cc].z, kv.z, a);
                a = fmaf(q[cc].w, kv.w, a);
            }
            a += __shfl_xor_sync(0xffffffffu, a, 1);
            a += __shfl_xor_sync(0xffffffffu, a, 2);
            s[j] = a;
        }
        if (kb + 31 > qrow) {
#pragma unroll
            for (int j = 0; j < 32; j++)
                if (kb + j > qrow) s[j] = -1e30f;
        }
        float mnew = m;
#pragma unroll
        for (int j = 0; j < 32; j++) mnew = fmaxf(mnew, s[j]);
        float corr = __expf(m - mnew);
        m = mnew;
        l *= corr;
#pragma unroll
        for (int cc = 0; cc < 8; cc++) {
            o[cc].x *= corr; o[cc].y *= corr; o[cc].z *= corr; o[cc].w *= corr;
        }
#pragma unroll
        for (int j = 0; j < 32; j++) {
            float p = __expf(s[j] - mnew);
            l += p;
            s[j] = p;
        }
#pragma unroll
        for (int j = 0; j < 32; j++) {
            float p = s[j];
#pragma unroll
            for (int cc = 0; cc < 8; cc++) {
                float4 vv = Vt[j][cc * 4 + quad];
                o[cc].x = fmaf(p, vv.x, o[cc].x);
                o[cc].y = fmaf(p, vv.y, o[cc].y);
                o[cc].z = fmaf(p, vv.z, o[cc].z);
                o[cc].w = fmaf(p, vv.w, o[cc].w);
            }
        }
    }

    float inv = 1.f / l;
    float* ob = out + (size_t)(b * SS + qrow) * DD + h * DHH;
#pragma unroll
    for (int cc = 0; cc < 8; cc++) {
        float4 v = o[cc];
        v.x *= inv; v.y *= inv; v.z *= inv; v.w *= inv;
        *(float4*)(ob + cc * 16 + quad * 4) = v;
    }
}

// ============================================================================
// Residual-add + LayerNorm, row length 1024, one block/row, 256 threads.
// MODE 0: g_x = LN(aArg + g_tmp)          (aArg = src)
// MODE 1: outArg = LN(g_x + g_tmp)
// Scratch buffers resolved in device code; only harness pointers are args.
// ============================================================================
template<int MODE>
__global__ __launch_bounds__(256) void add_ln_kernel(
    const float* __restrict__ aArg, const float* __restrict__ g,
    const float* __restrict__ beta, float* __restrict__ outArg)
{
    const float* __restrict__ a = (MODE == 0) ? aArg : g_x;
    const float* __restrict__ r = g_tmp;
    float* __restrict__ out = (MODE == 0) ? g_x : outArg;

    __shared__ float red[16];
    const int row = blockIdx.x;
    const int tid = threadIdx.x;

    const float4 va = ((const float4*)(a + (size_t)row * DD))[tid];
    const float4 vr = ((const float4*)(r + (size_t)row * DD))[tid];
    float v0 = va.x + vr.x, v1 = va.y + vr.y, v2 = va.z + vr.z, v3 = va.w + vr.w;

    float s  = v0 + v1 + v2 + v3;
    float sq = v0*v0 + v1*v1 + v2*v2 + v3*v3;
#pragma unroll
    for (int off = 16; off; off >>= 1) {
        s  += __shfl_xor_sync(0xffffffffu, s,  off);
        sq += __shfl_xor_sync(0xffffffffu, sq, off);
    }
    if ((tid & 31) == 0) { red[tid >> 5] = s; red[8 + (tid >> 5)] = sq; }
    __syncthreads();
    s  = red[0] + red[1] + red[2] + red[3] + red[4] + red[5] + red[6] + red[7];
    sq = red[8] + red[9] + red[10] + red[11] + red[12] + red[13] + red[14] + red[15];

    const float mean = s * (1.f / 1024.f);
    const float var  = sq * (1.f / 1024.f) - mean * mean;
    const float inv  = rsqrtf(var + 1e-5f);

    const int col = tid * 4;
    const float4 gg = *(const float4*)(g + col);
    const float4 bb = *(const float4*)(beta + col);
    float4 ov;
    ov.x = (v0 - mean) * inv * gg.x + bb.x;
    ov.y = (v1 - mean) * inv * gg.y + bb.y;
    ov.z = (v2 - mean) * inv * gg.z + bb.z;
    ov.w = (v3 - mean) * inv * gg.w + bb.w;
    ((float4*)(out + (size_t)row * DD))[tid] = ov;
}

// ============================================================================
// launch — kernel launches only; scratch never crosses the host boundary
// ============================================================================
extern "C" void kernel_launch(void* const* d_in, const int* in_sizes, int n_in,
                              void* d_out, int out_size)
{
    const float* src   = (const float*)d_in[0];
    const float* w_qkv = (const float*)d_in[1];
    const float* w_out = (const float*)d_in[2];
    const float* w1    = (const float*)d_in[3];
    const float* b1    = (const float*)d_in[4];
    const float* w2    = (const float*)d_in[5];
    const float* b2    = (const float*)d_in[6];
    const float* g1    = (const float*)d_in[7];
    const float* beta1 = (const float*)d_in[8];
    const float* g2    = (const float*)d_in[9];
    const float* beta2 = (const float*)d_in[10];
    float* out = (float*)d_out;

    // 1) g_qkv = src @ w_qkv                       [8192,3072]
    sgemm_kernel<0,0,0><<<dim3(3*DD/128, ROWS/128), 256>>>(src, w_qkv, nullptr,
                                                           ROWS, 3*DD, DD);
    // 2) g_attn = causal_flash_attention(g_qkv)    [8192,1024]
    attn_kernel<<<dim3(SS/64, HH, BB), 256>>>();
    // 3) g_tmp = g_attn @ w_out
    sgemm_kernel<0,1,1><<<dim3(DD/128, ROWS/128), 256>>>(nullptr, w_out, nullptr,
                                                         ROWS, DD, DD);
    // 4) g_x = LN(src + g_tmp)
    add_ln_kernel<0><<<ROWS, 256>>>(src, g1, beta1, nullptr);
    // 5) g_ff1 = relu(g_x @ w1 + b1)
    sgemm_kernel<2,2,2><<<dim3(DFF/128, ROWS/128), 256>>>(nullptr, w1, b1,
                                                          ROWS, DFF, DD);
    // 6) g_tmp = g_ff1 @ w2 + b2
    sgemm_kernel<1,3,1><<<dim3(DD/128, ROWS/128), 256>>>(nullptr, w2, b2,
                                                         ROWS, DD, DFF);
    // 7) out = LN(g_x + g_tmp)
    add_ln_kernel<1><<<ROWS, 256>>>(nullptr, g2, beta2, out);
}

// round 17
// speedup vs baseline: 1.6434x; 1.6418x over previous
#include <cuda_runtime.h>
#include <cuda_bf16.h>
#include <cstdint>
#include <math.h>

// Problem constants
#define BB 4
#define SS 2048
#define DD 1024
#define HH 8
#define DHH 128
#define DFF 4096
#define ROWS (BB*SS)   // 8192

// -------- scratch (device globals; referenced ONLY from device code) --------
__device__ __align__(1024) float g_qkv [ROWS * 3 * DD];
__device__ __align__(1024) float g_attn[ROWS * DD];
__device__ __align__(1024) float g_x   [ROWS * DD];
__device__ __align__(1024) float g_tmp [ROWS * DD];
__device__ __align__(1024) __nv_bfloat16 g_aH[ROWS * DD];
__device__ __align__(1024) __nv_bfloat16 g_aL[ROWS * DD];
__device__ __align__(1024) __nv_bfloat16 g_fH[ROWS * DFF];
__device__ __align__(1024) __nv_bfloat16 g_fL[ROWS * DFF];
__device__ __align__(1024) __nv_bfloat16 g_wH[DFF * DD];
__device__ __align__(1024) __nv_bfloat16 g_wL[DFF * DD];

// ============================ PTX helpers (baseline, non-'a') ===============
__device__ __forceinline__ uint32_t smem_to_u32(const void* p) {
    uint32_t a;
    asm("{ .reg .u64 t; cvta.to.shared.u64 t, %1; cvt.u32.u64 %0, t; }"
        : "=r"(a) : "l"(p));
    return a;
}
#define CP_ASYNC16(s, g) \
    asm volatile("cp.async.cg.shared.global [%0], [%1], 16;" :: "r"(s), "l"(g) : "memory")
#define CP_COMMIT() asm volatile("cp.async.commit_group;" ::: "memory")
#define CP_WAIT(n)  asm volatile("cp.async.wait_group %0;" :: "n"(n) : "memory")

__device__ __forceinline__ void ldsm4(uint32_t* r, uint32_t addr) {
    asm volatile("ldmatrix.sync.aligned.m8n8.x4.shared.b16 {%0,%1,%2,%3}, [%4];"
        : "=r"(r[0]), "=r"(r[1]), "=r"(r[2]), "=r"(r[3]) : "r"(addr));
}
__device__ __forceinline__ void mma16816(float* c, const uint32_t* a, const uint32_t* b) {
    asm volatile("mma.sync.aligned.m16n8k16.row.col.f32.bf16.bf16.f32 "
        "{%0,%1,%2,%3}, {%4,%5,%6,%7}, {%8,%9}, {%0,%1,%2,%3};"
        : "+f"(c[0]), "+f"(c[1]), "+f"(c[2]), "+f"(c[3])
        : "r"(a[0]), "r"(a[1]), "r"(a[2]), "r"(a[3]), "r"(b[0]), "r"(b[1]));
}
__device__ __forceinline__ uint32_t pack_bf2(__nv_bfloat16 a, __nv_bfloat16 b) {
    __nv_bfloat162 t; t.x = a; t.y = b;
    return *reinterpret_cast<uint32_t*>(&t);
}

// ============================================================================
// bf16x3 GEMM: C[M,N] = (A_hi+A_lo)[M,K] @ (W_hi+W_lo)^T
// mma.sync m16n8k16, 128x128 CTA tile, BK=32, 256 thr (2x4 warps, 64x32/warp)
// smem rows padded to 80B -> conflict-free ldmatrix without swizzle.
// ASEL: 0 = g_aH/g_aL, 1 = g_fH/g_fL
// EPI:  0 fp32 store (CSEL 0=g_qkv, 1=g_tmp); 1 +bias->g_tmp;
//       2 +bias+relu+hi/lo split -> g_fH/g_fL
// ============================================================================
#define RSTRIDE 80                       // bytes per 32-bf16 smem row (64B+16B pad)
#define TILE_SZ (128 * RSTRIDE)          // 10240 B
#define STAGE_SZ (4 * TILE_SZ)           // Ah, Al, Bh, Bl
#define GEMM_SMEM (2 * STAGE_SZ)         // 81920 B

extern __shared__ char dsm[];

__device__ __forceinline__ void load_stage(
    uint32_t sb, int stage, int kc, int by, int bx, int K,
    const __nv_bfloat16* __restrict__ aH, const __nv_bfloat16* __restrict__ aL)
{
    const int tid = threadIdx.x;
    const size_t koff = (size_t)kc * 32;
    const uint32_t tbase = sb + (uint32_t)stage * STAGE_SZ;
#pragma unroll
    for (int i = 0; i < 8; i++) {
        const int idx = i * 256 + tid;          // 0..2047
        const int buf = idx >> 9;               // 0=Ah 1=Al 2=Bh 3=Bl
        const int rem = idx & 511;
        const int r = rem >> 2, ch = rem & 3;   // row 0..127, 16B chunk 0..3
        uint32_t daddr = tbase + buf * TILE_SZ + (uint32_t)(r * RSTRIDE + ch * 16);
        const __nv_bfloat16* sp;
        if (buf == 0)      sp = aH   + ((size_t)(by * 128 + r)) * K + koff + ch * 8;
        else if (buf == 1) sp = aL   + ((size_t)(by * 128 + r)) * K + koff + ch * 8;
        else if (buf == 2) sp = g_wH + ((size_t)(bx * 128 + r)) * K + koff + ch * 8;
        else               sp = g_wL + ((size_t)(bx * 128 + r)) * K + koff + ch * 8;
        CP_ASYNC16(daddr, sp);
    }
}

template<int EPI, int ASEL, int CSEL>
__global__ __launch_bounds__(256) void tc_gemm(const float* __restrict__ bias, int N, int K)
{
    const __nv_bfloat16* __restrict__ aH = (ASEL == 0) ? g_aH : g_fH;
    const __nv_bfloat16* __restrict__ aL = (ASEL == 0) ? g_aL : g_fL;

    const uint32_t sb = smem_to_u32(dsm);
    const int tid = threadIdx.x, wid = tid >> 5, lane = tid & 31;
    const int bx = blockIdx.x, by = blockIdx.y;
    const int wm = (wid >> 2) * 64;         // warp M offset (0/64)
    const int wn = (wid & 3) * 32;          // warp N offset (0..96)
    const int l8 = lane & 7, grp = lane >> 3;

    float acc[4][4][4];
#pragma unroll
    for (int mt = 0; mt < 4; mt++)
#pragma unroll
        for (int nt = 0; nt < 4; nt++)
#pragma unroll
            for (int i = 0; i < 4; i++) acc[mt][nt][i] = 0.f;

    // ldmatrix lane-address components
    // A tiles (m16k16): rows m = wm + mt*16 + (grp&1)*8 + l8 ; k = ks*16 + (grp>>1)*8
    const uint32_t a_row = (uint32_t)(wm + (grp & 1) * 8 + l8) * RSTRIDE
                         + (uint32_t)((grp >> 1) * 8) * 2;
    // B tiles (n16k16 per x4): n = wn + p*16 + (grp>>1)*8 + l8 ; k = ks*16 + (grp&1)*8
    const uint32_t b_row = (uint32_t)(wn + (grp >> 1) * 8 + l8) * RSTRIDE
                         + (uint32_t)((grp & 1) * 8) * 2;

    const int NKC = K >> 5;
    load_stage(sb, 0, 0, by, bx, K, aH, aL);
    CP_COMMIT();

    for (int kc = 0; kc < NKC; kc++) {
        const int s = kc & 1;
        if (kc + 1 < NKC) {
            load_stage(sb, 1 - s, kc + 1, by, bx, K, aH, aL);
            CP_COMMIT();
            CP_WAIT(1);
        } else {
            CP_WAIT(0);
        }
        __syncthreads();

        const uint32_t base = sb + (uint32_t)s * STAGE_SZ;
        const uint32_t bAh = base + a_row;
        const uint32_t bAl = base + TILE_SZ + a_row;
        const uint32_t bBh = base + 2 * TILE_SZ + b_row;
        const uint32_t bBl = base + 3 * TILE_SZ + b_row;

#pragma unroll
        for (int ks = 0; ks < 2; ks++) {
            uint32_t ah[4][4], al[4][4];
#pragma unroll
            for (int mt = 0; mt < 4; mt++) {
                const uint32_t off = (uint32_t)(mt * 16) * RSTRIDE + (uint32_t)(ks * 16) * 2;
                ldsm4(ah[mt], bAh + off);
                ldsm4(al[mt], bAl + off);
            }
            uint32_t bh[4][2], bl[4][2];
#pragma unroll
            for (int p = 0; p < 2; p++) {
                const uint32_t off = (uint32_t)(p * 16) * RSTRIDE + (uint32_t)(ks * 16) * 2;
                uint32_t t[4];
                ldsm4(t, bBh + off);
                bh[2*p][0] = t[0]; bh[2*p][1] = t[1];
                bh[2*p+1][0] = t[2]; bh[2*p+1][1] = t[3];
                ldsm4(t, bBl + off);
                bl[2*p][0] = t[0]; bl[2*p][1] = t[1];
                bl[2*p+1][0] = t[2]; bl[2*p+1][1] = t[3];
            }
#pragma unroll
            for (int mt = 0; mt < 4; mt++)
#pragma unroll
                for (int nt = 0; nt < 4; nt++) {
                    mma16816(acc[mt][nt], ah[mt], bh[nt]);
                    mma16816(acc[mt][nt], al[mt], bh[nt]);
                    mma16816(acc[mt][nt], ah[mt], bl[nt]);
                }
        }
        __syncthreads();
    }

    // ---- epilogue ----
    const int q = lane >> 2, rr = lane & 3;          // row t/4, col pair 2*(t%4)
#pragma unroll
    for (int mt = 0; mt < 4; mt++) {
#pragma unroll
        for (int half = 0; half < 2; half++) {
            const int m = by * 128 + wm + mt * 16 + half * 8 + q;
#pragma unroll
            for (int nt = 0; nt < 4; nt++) {
                const int col = bx * 128 + wn + nt * 8 + 2 * rr;
                float v0 = acc[mt][nt][2 * half + 0];
                float v1 = acc[mt][nt][2 * half + 1];
                if (EPI == 0) {
                    float* C = (CSEL == 0) ? g_qkv : g_tmp;
                    float2 o; o.x = v0; o.y = v1;
                    *(float2*)(C + (size_t)m * N + col) = o;
                } else if (EPI == 1) {
                    float2 o;
                    o.x = v0 + bias[col];
                    o.y = v1 + bias[col + 1];
                    *(float2*)(g_tmp + (size_t)m * N + col) = o;
                } else {
                    float w0 = fmaxf(v0 + bias[col], 0.f);
                    float w1 = fmaxf(v1 + bias[col + 1], 0.f);
                    __nv_bfloat16 h0 = __float2bfloat16_rn(w0);
                    __nv_bfloat16 h1 = __float2bfloat16_rn(w1);
                    __nv_bfloat16 lo0 = __float2bfloat16_rn(w0 - __bfloat162float(h0));
                    __nv_bfloat16 lo1 = __float2bfloat16_rn(w1 - __bfloat162float(h1));
                    *(uint32_t*)(g_fH + (size_t)m * N + col) = pack_bf2(h0, h1);
                    *(uint32_t*)(g_fL + (size_t)m * N + col) = pack_bf2(lo0, lo1);
                }
            }
        }
    }
}

// ============================================================================
// Activation split: fp32 -> g_aH/g_aL. SEL: 0=arg(src), 1=g_attn, 2=g_x
// ============================================================================
template<int SEL>
__global__ __launch_bounds__(256) void cvt_act_kernel(const float* __restrict__ inArg)
{
    const float* __restrict__ in = (SEL == 0) ? inArg : (SEL == 1) ? g_attn : g_x;
    const size_t i = (size_t)blockIdx.x * 256 + threadIdx.x;     // over float4s
    float4 v = ((const float4*)in)[i];
    __nv_bfloat16 h0 = __float2bfloat16_rn(v.x), h1 = __float2bfloat16_rn(v.y);
    __nv_bfloat16 h2 = __float2bfloat16_rn(v.z), h3 = __float2bfloat16_rn(v.w);
    __nv_bfloat16 l0 = __float2bfloat16_rn(v.x - __bfloat162float(h0));
    __nv_bfloat16 l1 = __float2bfloat16_rn(v.y - __bfloat162float(h1));
    __nv_bfloat16 l2 = __float2bfloat16_rn(v.z - __bfloat162float(h2));
    __nv_bfloat16 l3 = __float2bfloat16_rn(v.w - __bfloat162float(h3));
    ((uint32_t*)g_aH)[2*i+0] = pack_bf2(h0, h1);
    ((uint32_t*)g_aH)[2*i+1] = pack_bf2(h2, h3);
    ((uint32_t*)g_aL)[2*i+0] = pack_bf2(l0, l1);
    ((uint32_t*)g_aL)[2*i+1] = pack_bf2(l2, l3);
}

// ============================================================================
// Weight transpose + split: W[K,N] fp32 -> g_wH/g_wL[N,K] bf16 (K-major)
// ============================================================================
__global__ __launch_bounds__(256) void cvt_wT_kernel(const float* __restrict__ W, int K, int N)
{
    __shared__ float tile[32][33];
    const int tx = threadIdx.x, ty = threadIdx.y;
    const int n0 = blockIdx.x * 32, k0 = blockIdx.y * 32;
#pragma unroll
    for (int i = 0; i < 4; i++)
        tile[ty + 8*i][tx] = W[(size_t)(k0 + ty + 8*i) * N + n0 + tx];
    __syncthreads();
#pragma unroll
    for (int i = 0; i < 4; i++) {
        float v = tile[tx][ty + 8*i];
        __nv_bfloat16 h = __float2bfloat16_rn(v);
        __nv_bfloat16 l = __float2bfloat16_rn(v - __bfloat162float(h));
        size_t idx = (size_t)(n0 + ty + 8*i) * K + k0 + tx;
        g_wH[idx] = h;
        g_wL[idx] = l;
    }
}

// ============================================================================
// Causal flash attention (fp32, unchanged — proven correct)
// ============================================================================
__global__ __launch_bounds__(256) void attn_kernel()
{
    __shared__ float4 Kt[32][32];
    __shared__ float4 Vt[32][32];

    const float* __restrict__ qkv = g_qkv;
    float* __restrict__ out = g_attn;

    const int b = blockIdx.z, h = blockIdx.y, qt = blockIdx.x;
    const int tid = threadIdx.x;
    const int row = tid >> 2, quad = tid & 3;
    const int qrow = qt * 64 + row;
    const float scale = 0.08838834764831845f;

    const float* qbase = qkv + (size_t)(b * SS + qrow) * (3 * DD) + h * DHH;
    float4 q[8];
#pragma unroll
    for (int cc = 0; cc < 8; cc++) {
        float4 t = *(const float4*)(qbase + cc * 16 + quad * 4);
        t.x *= scale; t.y *= scale; t.z *= scale; t.w *= scale;
        q[cc] = t;
    }

    float4 o[8];
#pragma unroll
    for (int cc = 0; cc < 8; cc++) o[cc] = make_float4(0.f, 0.f, 0.f, 0.f);
    float m = -1e30f, l = 0.f;

    const int ntiles = 2 * qt + 2;
    for (int kt = 0; kt < ntiles; kt++) {
        const int kb = kt * 32;
        __syncthreads();
#pragma unroll
        for (int i = 0; i < 4; i++) {
            int f = tid + i * 256;
            int r = f >> 5, c = f & 31;
            size_t grow = (size_t)(b * SS + kb + r) * (3 * DD) + h * DHH;
            Kt[r][c] = *(const float4*)(qkv + grow + DD + c * 4);
            Vt[r][c] = *(const float4*)(qkv + grow + 2 * DD + c * 4);
        }
        __syncthreads();

        float s[32];
#pragma unroll
        for (int j = 0; j < 32; j++) {
            float a = 0.f;
#pragma unroll
            for (int cc = 0; cc < 8; cc++) {
                float4 kv = Kt[j][cc * 4 + quad];
                a = fmaf(q[cc].x, kv.x, a);
                a = fmaf(q[cc].y, kv.y, a);
                a = fmaf(q[cc].z, kv.z, a);
                a = fmaf(q[cc].w, kv.w, a);
            }
            a += __shfl_xor_sync(0xffffffffu, a, 1);
            a += __shfl_xor_sync(0xffffffffu, a, 2);
            s[j] = a;
        }
        if (kb + 31 > qrow) {
#pragma unroll
            for (int j = 0; j < 32; j++)
                if (kb + j > qrow) s[j] = -1e30f;
        }
        float mnew = m;
#pragma unroll
        for (int j = 0; j < 32; j++) mnew = fmaxf(mnew, s[j]);
        float corr = __expf(m - mnew);
        m = mnew;
        l *= corr;
#pragma unroll
        for (int cc = 0; cc < 8; cc++) {
            o[cc].x *= corr; o[cc].y *= corr; o[cc].z *= corr; o[cc].w *= corr;
        }
#pragma unroll
        for (int j = 0; j < 32; j++) {
            float p = __expf(s[j] - mnew);
            l += p;
            s[j] = p;
        }
#pragma unroll
        for (int j = 0; j < 32; j++) {
            float p = s[j];
#pragma unroll
            for (int cc = 0; cc < 8; cc++) {
                float4 vv = Vt[j][cc * 4 + quad];
                o[cc].x = fmaf(p, vv.x, o[cc].x);
                o[cc].y = fmaf(p, vv.y, o[cc].y);
                o[cc].z = fmaf(p, vv.z, o[cc].z);
                o[cc].w = fmaf(p, vv.w, o[cc].w);
            }
        }
    }

    float inv = 1.f / l;
    float* ob = out + (size_t)(b * SS + qrow) * DD + h * DHH;
#pragma unroll
    for (int cc = 0; cc < 8; cc++) {
        float4 v = o[cc];
        v.x *= inv; v.y *= inv; v.z *= inv; v.w *= inv;
        *(float4*)(ob + cc * 16 + quad * 4) = v;
    }
}

// ============================================================================
// Residual-add + LayerNorm. MODE 0: g_x = LN(arg + g_tmp); MODE 1: out = LN(g_x + g_tmp)
// ============================================================================
template<int MODE>
__global__ __launch_bounds__(256) void add_ln_kernel(
    const float* __restrict__ aArg, const float* __restrict__ g,
    const float* __restrict__ beta, float* __restrict__ outArg)
{
    const float* __restrict__ a = (MODE == 0) ? aArg : g_x;
    const float* __restrict__ r = g_tmp;
    float* __restrict__ out = (MODE == 0) ? g_x : outArg;

    __shared__ float red[16];
    const int row = blockIdx.x;
    const int tid = threadIdx.x;

    const float4 va = ((const float4*)(a + (size_t)row * DD))[tid];
    const float4 vr = ((const float4*)(r + (size_t)row * DD))[tid];
    float v0 = va.x + vr.x, v1 = va.y + vr.y, v2 = va.z + vr.z, v3 = va.w + vr.w;

    float s  = v0 + v1 + v2 + v3;
    float sq = v0*v0 + v1*v1 + v2*v2 + v3*v3;
#pragma unroll
    for (int off = 16; off; off >>= 1) {
        s  += __shfl_xor_sync(0xffffffffu, s,  off);
        sq += __shfl_xor_sync(0xffffffffu, sq, off);
    }
    if ((tid & 31) == 0) { red[tid >> 5] = s; red[8 + (tid >> 5)] = sq; }
    __syncthreads();
    s  = red[0] + red[1] + red[2] + red[3] + red[4] + red[5] + red[6] + red[7];
    sq = red[8] + red[9] + red[10] + red[11] + red[12] + red[13] + red[14] + red[15];

    const float mean = s * (1.f / 1024.f);
    const float var  = sq * (1.f / 1024.f) - mean * mean;
    const float inv  = rsqrtf(var + 1e-5f);

    const int col = tid * 4;
    const float4 gg = *(const float4*)(g + col);
    const float4 bb = *(const float4*)(beta + col);
    float4 ov;
    ov.x = (v0 - mean) * inv * gg.x + bb.x;
    ov.y = (v1 - mean) * inv * gg.y + bb.y;
    ov.z = (v2 - mean) * inv * gg.z + bb.z;
    ov.w = (v3 - mean) * inv * gg.w + bb.w;
    ((float4*)(out + (size_t)row * DD))[tid] = ov;
}

// ============================================================================
// launch
// ============================================================================
extern "C" void kernel_launch(void* const* d_in, const int* in_sizes, int n_in,
                              void* d_out, int out_size)
{
    const float* src   = (const float*)d_in[0];
    const float* w_qkv = (const float*)d_in[1];
    const float* w_out = (const float*)d_in[2];
    const float* w1    = (const float*)d_in[3];
    const float* b1    = (const float*)d_in[4];
    const float* w2    = (const float*)d_in[5];
    const float* b2    = (const float*)d_in[6];
    const float* g1    = (const float*)d_in[7];
    const float* beta1 = (const float*)d_in[8];
    const float* g2    = (const float*)d_in[9];
    const float* beta2 = (const float*)d_in[10];
    float* out = (float*)d_out;

    cudaFuncSetAttribute(tc_gemm<0,0,0>, cudaFuncAttributeMaxDynamicSharedMemorySize, GEMM_SMEM);
    cudaFuncSetAttribute(tc_gemm<0,0,1>, cudaFuncAttributeMaxDynamicSharedMemorySize, GEMM_SMEM);
    cudaFuncSetAttribute(tc_gemm<2,0,0>, cudaFuncAttributeMaxDynamicSharedMemorySize, GEMM_SMEM);
    cudaFuncSetAttribute(tc_gemm<1,1,1>, cudaFuncAttributeMaxDynamicSharedMemorySize, GEMM_SMEM);

    const int nact4 = ROWS * DD / 4 / 256;   // 8192 blocks

    // 1) split src -> aH/aL ; transpose+split w_qkv
    cvt_act_kernel<0><<<nact4, 256>>>(src);
    cvt_wT_kernel<<<dim3(3*DD/32, DD/32), dim3(32,8)>>>(w_qkv, DD, 3*DD);
    // 2) g_qkv = src @ w_qkv   (fp32 out for attention)
    tc_gemm<0,0,0><<<dim3(3*DD/128, ROWS/128), 256, GEMM_SMEM>>>(nullptr, 3*DD, DD);
    // 3) attention
    attn_kernel<<<dim3(SS/64, HH, BB), 256>>>();
    // 4) split g_attn ; transpose+split w_out ; g_tmp = g_attn @ w_out
    cvt_act_kernel<1><<<nact4, 256>>>(nullptr);
    cvt_wT_kernel<<<dim3(DD/32, DD/32), dim3(32,8)>>>(w_out, DD, DD);
    tc_gemm<0,0,1><<<dim3(DD/128, ROWS/128), 256, GEMM_SMEM>>>(nullptr, DD, DD);
    // 5) g_x = LN(src + g_tmp)
    add_ln_kernel<0><<<ROWS, 256>>>(src, g1, beta1, nullptr);
    // 6) split g_x ; transpose+split w1 ; ff1 = relu(g_x@w1+b1) -> g_fH/g_fL
    cvt_act_kernel<2><<<nact4, 256>>>(nullptr);
    cvt_wT_kernel<<<dim3(DFF/32, DD/32), dim3(32,8)>>>(w1, DD, DFF);
    tc_gemm<2,0,0><<<dim3(DFF/128, ROWS/128), 256, GEMM_SMEM>>>(b1, DFF, DD);
    // 7) transpose+split w2 ; g_tmp = ff1 @ w2 + b2   (K=4096)
    cvt_wT_kernel<<<dim3(DD/32, DFF/32), dim3(32,8)>>>(w2, DFF, DD);
    tc_gemm<1,1,1><<<dim3(DD/128, ROWS/128), 256, GEMM_SMEM>>>(b2, DD, DFF);
    // 8) out = LN(g_x + g_tmp)
    add_ln_kernel<1><<<ROWS, 256>>>(nullptr, g2, beta2, out);
}